// round 12
// baseline (speedup 1.0000x reference)
#include <cuda_runtime.h>

#define IH 4096
#define IW 4096
#define OH 4082
#define OW 4082

#define TILE_R 64          // output rows per block (2 rows per lane)
#define TILE_C 96          // output cols per block (6 warps x 16)
#define NTHR   192
#define IN_R   78          // TILE_R + 14 input rows staged
#define PITCH_F 128        // smem row pitch in floats
#define PITCH_B 512
#define LOAD_F4 28         // float4 per staged row

typedef unsigned long long ull;

__device__ __forceinline__ ull fma2(ull a, ull b, ull c) {
    ull d;
    asm("fma.rn.f32x2 %0, %1, %2, %3;" : "=l"(d) : "l"(a), "l"(b), "l"(c));
    return d;
}
__device__ __forceinline__ ull add2(ull a, ull b) {
    ull d;
    asm("add.rn.f32x2 %0, %1, %2;" : "=l"(d) : "l"(a), "l"(b));
    return d;
}
__device__ __forceinline__ ull mkpair(unsigned lo, unsigned hi) {
    ull d;
    asm("mov.b64 %0, {%1, %2};" : "=l"(d) : "r"(lo), "r"(hi));
    return d;
}

// One weight row (15 taps in padded 16-ull rows) applied to 8 f32x2 accs.
// kx=2m -> pair a[p+m] with w2[m].x ; kx=2m+1 -> pair b[p+m] with w2[m].y
__device__ __forceinline__ void conv_row(ull* acc, const ull* a, const ull* b,
                                         const ulonglong2* __restrict__ wr2) {
#pragma unroll
    for (int m = 0; m < 8; ++m) {
        ulonglong2 w2 = wr2[m];          // broadcast LDS.128: taps 2m, 2m+1
#pragma unroll
        for (int p = 0; p < 8; ++p) acc[p] = fma2(a[p + m], w2.x, acc[p]);
        if (m < 7) {
#pragma unroll
            for (int p = 0; p < 8; ++p) acc[p] = fma2(b[p + m], w2.y, acc[p]);
        }
    }
}

// Phase 1: issue the 8 shared loads for input row ir (raw, no expansion).
__device__ __forceinline__ void load_raw(const float* sA, int ir, int c0,
                                         ulonglong2* t, ull* tlast) {
    const unsigned xv = (((unsigned)ir) >> 1) & 7u;
    const char* rowp = reinterpret_cast<const char*>(sA) + ir * PITCH_B;
#pragma unroll
    for (int i = 0; i < 7; ++i)
        t[i] = *reinterpret_cast<const ulonglong2*>(
            rowp + ((unsigned)((c0 + i) ^ xv) << 4));
    *tlast = *reinterpret_cast<const ull*>(rowp + ((unsigned)((c0 + 7) ^ xv) << 4));
}

// Phase 2: expand raw loads into aligned pairs a[0..14] and odd pairs b[0..13].
__device__ __forceinline__ void expand(const ulonglong2* t, ull tlast,
                                       ull* a, ull* b) {
#pragma unroll
    for (int i = 0; i < 7; ++i) { a[2 * i] = t[i].x; a[2 * i + 1] = t[i].y; }
    a[14] = tlast;
#pragma unroll
    for (int q = 0; q < 14; ++q)
        b[q] = mkpair((unsigned)(a[q] >> 32), (unsigned)(a[q + 1] & 0xffffffffULL));
}

__global__ void __launch_bounds__(NTHR, 2)
conv15_kernel(const float* __restrict__ X, const float* __restrict__ Wt,
              const float* __restrict__ bias, float* __restrict__ out) {
    __shared__ float sA[IN_R * PITCH_F];
    __shared__ __align__(16) ull sW[15 * 16];   // row j at sW+16*j (padded)

    const int tid = threadIdx.x;
    const int gro = blockIdx.y * TILE_R;
    const int gco = blockIdx.x * TILE_C;

    // Stage weights as duplicated f32x2 pairs into padded rows.
    for (int i = tid; i < 225; i += NTHR) {
        int row = i / 15;
        int t = i - row * 15;
        unsigned wb = __float_as_uint(Wt[i]);
        sW[row * 16 + t] = mkpair(wb, wb);
    }

    // Stage the input tile with 16B-granularity XOR swizzle: chunk ^ ((row>>1)&7).
    for (int idx = tid; idx < IN_R * LOAD_F4; idx += NTHR) {
        int r = idx / LOAD_F4;
        int c4 = idx - r * LOAD_F4;
        int gr = gro + r;
        int gc = gco + c4 * 4;
        float4 v = make_float4(0.f, 0.f, 0.f, 0.f);
        if (gr < IH && gc < IW)
            v = *reinterpret_cast<const float4*>(X + (size_t)gr * IW + gc);
        unsigned xv = (((unsigned)r) >> 1) & 7u;
        *reinterpret_cast<float4*>(sA + r * PITCH_F + (((unsigned)c4 ^ xv) << 2)) = v;
    }
    __syncthreads();

    const int warp = tid >> 5;         // 0..5 -> 16-col strip
    const int lane = tid & 31;
    const int c0 = warp * 4;           // window base in 16B chunks
    const int r0 = lane * 2;           // two output rows per lane

    ull acc0[8], acc1[8];
#pragma unroll
    for (int p = 0; p < 8; ++p) { acc0[p] = 0ULL; acc1[p] = 0ULL; }

    ulonglong2 t[7];
    ull tlast;
    ull a[15], b[14];

    // acc0 (out row r0)   = sum_{ky} w[ky] * row(r0+ky)      -> row r uses w[r]
    // acc1 (out row r0+1) = sum_{ky} w[ky] * row(r0+1+ky)    -> row r uses w[r-1]

    // Prologue (uncovered): row0 -> acc0*w0 ; row1 -> acc0*w1.
    load_raw(sA, r0, c0, t, &tlast);
    expand(t, tlast, a, b);
    conv_row(acc0, a, b, reinterpret_cast<const ulonglong2*>(sW));

    load_raw(sA, r0 + 1, c0, t, &tlast);
    expand(t, tlast, a, b);
    conv_row(acc0, a, b, reinterpret_cast<const ulonglong2*>(sW + 16));

    // Steady state. Entering iteration j: a/b hold row j-1.
    //   1) issue LDS for row j (in flight)
    //   2) cover: acc1 += w[j-2] * row(j-1)      (120 FFMA2 of latency cover)
    //   3) expand row j; acc0 += w[j] * row j
#pragma unroll 1
    for (int j = 2; j <= 14; ++j) {
        load_raw(sA, r0 + j, c0, t, &tlast);
        conv_row(acc1, a, b, reinterpret_cast<const ulonglong2*>(sW + (j - 2) * 16));
        expand(t, tlast, a, b);
        conv_row(acc0, a, b, reinterpret_cast<const ulonglong2*>(sW + j * 16));
    }

    // Tail: a/b = row14. acc1 += w13*row14 (covers row15 load); then w14*row15.
    load_raw(sA, r0 + 15, c0, t, &tlast);
    conv_row(acc1, a, b, reinterpret_cast<const ulonglong2*>(sW + 13 * 16));
    expand(t, tlast, a, b);
    conv_row(acc1, a, b, reinterpret_cast<const ulonglong2*>(sW + 14 * 16));

    // Store: add bias, aligned 8B pairs (OW even -> pairs never straddle edge).
    const unsigned bb = __float_as_uint(bias[0]);
    const ull bpair = mkpair(bb, bb);
    const int oc0 = gco + warp * 16;

    {
        int orow = gro + r0;
        if (orow < OH) {
            float* op = out + (size_t)orow * OW;
#pragma unroll
            for (int p = 0; p < 8; ++p) {
                int oc = oc0 + 2 * p;
                if (oc < OW)
                    *reinterpret_cast<ull*>(op + oc) = add2(acc0[p], bpair);
            }
        }
    }
    {
        int orow = gro + r0 + 1;
        if (orow < OH) {
            float* op = out + (size_t)orow * OW;
#pragma unroll
            for (int p = 0; p < 8; ++p) {
                int oc = oc0 + 2 * p;
                if (oc < OW)
                    *reinterpret_cast<ull*>(op + oc) = add2(acc1[p], bpair);
            }
        }
    }
}

extern "C" void kernel_launch(void* const* d_in, const int* in_sizes, int n_in,
                              void* d_out, int out_size) {
    (void)in_sizes; (void)n_in; (void)out_size;
    const float* X = (const float*)d_in[0];
    const float* W = (const float*)d_in[1];
    const float* b = (const float*)d_in[2];
    float* out = (float*)d_out;

    cudaFuncSetAttribute(conv15_kernel,
                         cudaFuncAttributePreferredSharedMemoryCarveout,
                         cudaSharedmemCarveoutMaxShared);

    dim3 grid((OW + TILE_C - 1) / TILE_C, (OH + TILE_R - 1) / TILE_R);
    conv15_kernel<<<grid, NTHR>>>(X, W, b, out);
}

// round 13
// speedup vs baseline: 1.0856x; 1.0856x over previous
#include <cuda_runtime.h>

#define IH 4096
#define IW 4096
#define OH 4082
#define OW 4082

#define TILE_R 64          // output rows per block (2 rows per lane)
#define TILE_C 96          // output cols per block (6 warps x 16)
#define NTHR   192
#define IN_R   78          // TILE_R + 14 input rows staged
#define PITCH_F 128        // smem row pitch in floats
#define PITCH_B 512
#define LOAD_F4 28         // float4 per staged row

typedef unsigned long long ull;

__device__ __forceinline__ ull fma2(ull a, ull b, ull c) {
    ull d;
    asm("fma.rn.f32x2 %0, %1, %2, %3;" : "=l"(d) : "l"(a), "l"(b), "l"(c));
    return d;
}
__device__ __forceinline__ ull add2(ull a, ull b) {
    ull d;
    asm("add.rn.f32x2 %0, %1, %2;" : "=l"(d) : "l"(a), "l"(b));
    return d;
}
__device__ __forceinline__ ull mkpair(unsigned lo, unsigned hi) {
    ull d;
    asm("mov.b64 %0, {%1, %2};" : "=l"(d) : "r"(lo), "r"(hi));
    return d;
}

// Single-row variant (tile edges): one weight row onto one acc set.
__device__ __forceinline__ void conv_row(ull* acc, const ull* a, const ull* b,
                                         const ulonglong2* __restrict__ wr2) {
#pragma unroll
    for (int m = 0; m < 8; ++m) {
        ulonglong2 w2 = wr2[m];
#pragma unroll
        for (int p = 0; p < 8; ++p) acc[p] = fma2(a[p + m], w2.x, acc[p]);
        if (m < 7) {
#pragma unroll
            for (int p = 0; p < 8; ++p) acc[p] = fma2(b[p + m], w2.y, acc[p]);
        }
    }
}

// Dual-row interleaved: same input row feeds acc0 (w_hi = w[j]) and acc1
// (w_lo = w[j-1]). Consecutive FFMA2s share the 'a'/'b' operand (-> .reuse)
// and alternate between two independent dependency chains.
__device__ __forceinline__ void conv_row2(ull* acc0, ull* acc1,
                                          const ull* a, const ull* b,
                                          const ulonglong2* __restrict__ w_hi,
                                          const ulonglong2* __restrict__ w_lo) {
#pragma unroll
    for (int m = 0; m < 8; ++m) {
        ulonglong2 wh = w_hi[m];
        ulonglong2 wl = w_lo[m];
#pragma unroll
        for (int p = 0; p < 8; ++p) {
            acc0[p] = fma2(a[p + m], wh.x, acc0[p]);
            acc1[p] = fma2(a[p + m], wl.x, acc1[p]);
        }
        if (m < 7) {
#pragma unroll
            for (int p = 0; p < 8; ++p) {
                acc0[p] = fma2(b[p + m], wh.y, acc0[p]);
                acc1[p] = fma2(b[p + m], wl.y, acc1[p]);
            }
        }
    }
}

// Load the 30-float window (15 aligned pairs) for input row ir; build 14 odd pairs.
__device__ __forceinline__ void load_win(const float* sA, int ir, int c0,
                                         ull* a, ull* b) {
    const unsigned xv = (((unsigned)ir) >> 1) & 7u;
    const char* rowp = reinterpret_cast<const char*>(sA) + ir * PITCH_B;
#pragma unroll
    for (int i = 0; i < 7; ++i) {
        ulonglong2 t = *reinterpret_cast<const ulonglong2*>(
            rowp + ((unsigned)((c0 + i) ^ xv) << 4));
        a[2 * i] = t.x;
        a[2 * i + 1] = t.y;
    }
    a[14] = *reinterpret_cast<const ull*>(rowp + ((unsigned)((c0 + 7) ^ xv) << 4));
#pragma unroll
    for (int q = 0; q < 14; ++q)
        b[q] = mkpair((unsigned)(a[q] >> 32), (unsigned)(a[q + 1] & 0xffffffffULL));
}

__global__ void __launch_bounds__(NTHR, 3)
conv15_kernel(const float* __restrict__ X, const float* __restrict__ Wt,
              const float* __restrict__ bias, float* __restrict__ out) {
    __shared__ float sA[IN_R * PITCH_F];
    __shared__ __align__(16) ull sW[15 * 16];   // row j at sW+16*j (padded)

    const int tid = threadIdx.x;
    const int gro = blockIdx.y * TILE_R;
    const int gco = blockIdx.x * TILE_C;

    // Stage weights as duplicated f32x2 pairs into padded rows.
    for (int i = tid; i < 225; i += NTHR) {
        int row = i / 15;
        int t = i - row * 15;
        unsigned wb = __float_as_uint(Wt[i]);
        sW[row * 16 + t] = mkpair(wb, wb);
    }

    // Stage the input tile with 16B-granularity XOR swizzle: chunk ^ ((row>>1)&7).
    for (int idx = tid; idx < IN_R * LOAD_F4; idx += NTHR) {
        int r = idx / LOAD_F4;
        int c4 = idx - r * LOAD_F4;
        int gr = gro + r;
        int gc = gco + c4 * 4;
        float4 v = make_float4(0.f, 0.f, 0.f, 0.f);
        if (gr < IH && gc < IW)
            v = *reinterpret_cast<const float4*>(X + (size_t)gr * IW + gc);
        unsigned xv = (((unsigned)r) >> 1) & 7u;
        *reinterpret_cast<float4*>(sA + r * PITCH_F + (((unsigned)c4 ^ xv) << 2)) = v;
    }
    __syncthreads();

    const int warp = tid >> 5;         // 0..5 -> 16-col strip
    const int lane = tid & 31;
    const int c0 = warp * 4;           // window base in 16B chunks
    const int r0 = lane * 2;           // two output rows per lane

    ull acc0[8], acc1[8];
#pragma unroll
    for (int p = 0; p < 8; ++p) { acc0[p] = 0ULL; acc1[p] = 0ULL; }

    ull a[15], b[14];

    // acc0 (out row r0)   : row r0+j contributes with w[j]
    // acc1 (out row r0+1) : row r0+j contributes with w[j-1]

    // j = 0 : only acc0 (w0).
    load_win(sA, r0, c0, a, b);
    conv_row(acc0, a, b, reinterpret_cast<const ulonglong2*>(sW));

    // j = 1..14 : both rows, interleaved on the shared input row.
#pragma unroll 1
    for (int j = 1; j <= 14; ++j) {
        load_win(sA, r0 + j, c0, a, b);
        conv_row2(acc0, acc1, a, b,
                  reinterpret_cast<const ulonglong2*>(sW + j * 16),
                  reinterpret_cast<const ulonglong2*>(sW + (j - 1) * 16));
    }

    // j = 15 : only acc1 (w14).
    load_win(sA, r0 + 15, c0, a, b);
    conv_row(acc1, a, b, reinterpret_cast<const ulonglong2*>(sW + 14 * 16));

    // Store: add bias, aligned 8B pairs (OW even -> pairs never straddle edge).
    const unsigned bb = __float_as_uint(bias[0]);
    const ull bpair = mkpair(bb, bb);
    const int oc0 = gco + warp * 16;

    {
        int orow = gro + r0;
        if (orow < OH) {
            float* op = out + (size_t)orow * OW;
#pragma unroll
            for (int p = 0; p < 8; ++p) {
                int oc = oc0 + 2 * p;
                if (oc < OW)
                    *reinterpret_cast<ull*>(op + oc) = add2(acc0[p], bpair);
            }
        }
    }
    {
        int orow = gro + r0 + 1;
        if (orow < OH) {
            float* op = out + (size_t)orow * OW;
#pragma unroll
            for (int p = 0; p < 8; ++p) {
                int oc = oc0 + 2 * p;
                if (oc < OW)
                    *reinterpret_cast<ull*>(op + oc) = add2(acc1[p], bpair);
            }
        }
    }
}

extern "C" void kernel_launch(void* const* d_in, const int* in_sizes, int n_in,
                              void* d_out, int out_size) {
    (void)in_sizes; (void)n_in; (void)out_size;
    const float* X = (const float*)d_in[0];
    const float* W = (const float*)d_in[1];
    const float* b = (const float*)d_in[2];
    float* out = (float*)d_out;

    cudaFuncSetAttribute(conv15_kernel,
                         cudaFuncAttributePreferredSharedMemoryCarveout,
                         cudaSharedmemCarveoutMaxShared);

    dim3 grid((OW + TILE_C - 1) / TILE_C, (OH + TILE_R - 1) / TILE_R);
    conv15_kernel<<<grid, NTHR>>>(X, W, b, out);
}

// round 14
// speedup vs baseline: 1.0939x; 1.0077x over previous
#include <cuda_runtime.h>

#define IH 4096
#define IW 4096
#define OH 4082
#define OW 4082

#define TILE_R 64          // output rows per block (2 rows per lane)
#define TILE_C 96          // output cols per block (6 warps x 16)
#define NTHR   192
#define IN_R   78          // TILE_R + 14 input rows staged
#define PITCH_F 128        // smem row pitch in floats
#define PITCH_B 512
#define LOAD_F4 28         // float4 per staged row

typedef unsigned long long ull;

__device__ __forceinline__ ull fma2(ull a, ull b, ull c) {
    ull d;
    asm("fma.rn.f32x2 %0, %1, %2, %3;" : "=l"(d) : "l"(a), "l"(b), "l"(c));
    return d;
}
__device__ __forceinline__ ull add2(ull a, ull b) {
    ull d;
    asm("add.rn.f32x2 %0, %1, %2;" : "=l"(d) : "l"(a), "l"(b));
    return d;
}
__device__ __forceinline__ ull mkpair(unsigned lo, unsigned hi) {
    ull d;
    asm("mov.b64 %0, {%1, %2};" : "=l"(d) : "r"(lo), "r"(hi));
    return d;
}

// One weight row (15 taps in padded 16-ull rows) applied to 8 f32x2 accs.
// kx=2m -> pair a[p+m] with w2[m].x ; kx=2m+1 -> pair b[p+m] with w2[m].y
__device__ __forceinline__ void conv_row(ull* acc, const ull* a, const ull* b,
                                         const ulonglong2* __restrict__ wr2) {
#pragma unroll
    for (int m = 0; m < 8; ++m) {
        ulonglong2 w2 = wr2[m];          // broadcast LDS.128: taps 2m, 2m+1
#pragma unroll
        for (int p = 0; p < 8; ++p) acc[p] = fma2(a[p + m], w2.x, acc[p]);
        if (m < 7) {
#pragma unroll
            for (int p = 0; p < 8; ++p) acc[p] = fma2(b[p + m], w2.y, acc[p]);
        }
    }
}

// Issue the 8 shared loads for input row ir into the raw buffer t/tlast.
__device__ __forceinline__ void load_raw(const float* sA, int ir, int c0,
                                         ulonglong2* t, ull* tlast) {
    const unsigned xv = (((unsigned)ir) >> 1) & 7u;
    const char* rowp = reinterpret_cast<const char*>(sA) + ir * PITCH_B;
#pragma unroll
    for (int i = 0; i < 7; ++i)
        t[i] = *reinterpret_cast<const ulonglong2*>(
            rowp + ((unsigned)((c0 + i) ^ xv) << 4));
    *tlast = *reinterpret_cast<const ull*>(rowp + ((unsigned)((c0 + 7) ^ xv) << 4));
}

// Expand raw buffer into aligned pairs a[0..14] and odd pairs b[0..13].
// After this, t/tlast are dead and can be reused for the next prefetch.
__device__ __forceinline__ void expand(const ulonglong2* t, ull tlast,
                                       ull* a, ull* b) {
#pragma unroll
    for (int i = 0; i < 7; ++i) { a[2 * i] = t[i].x; a[2 * i + 1] = t[i].y; }
    a[14] = tlast;
#pragma unroll
    for (int q = 0; q < 14; ++q)
        b[q] = mkpair((unsigned)(a[q] >> 32), (unsigned)(a[q + 1] & 0xffffffffULL));
}

__global__ void __launch_bounds__(NTHR, 3)
conv15_kernel(const float* __restrict__ X, const float* __restrict__ Wt,
              const float* __restrict__ bias, float* __restrict__ out) {
    __shared__ float sA[IN_R * PITCH_F];
    __shared__ __align__(16) ull sW[15 * 16];   // row j at sW+16*j (padded)

    const int tid = threadIdx.x;
    const int gro = blockIdx.y * TILE_R;
    const int gco = blockIdx.x * TILE_C;

    // Stage weights as duplicated f32x2 pairs into padded rows.
    for (int i = tid; i < 225; i += NTHR) {
        int row = i / 15;
        int t = i - row * 15;
        unsigned wb = __float_as_uint(Wt[i]);
        sW[row * 16 + t] = mkpair(wb, wb);
    }

    // Stage the input tile with 16B-granularity XOR swizzle: chunk ^ ((row>>1)&7).
    for (int idx = tid; idx < IN_R * LOAD_F4; idx += NTHR) {
        int r = idx / LOAD_F4;
        int c4 = idx - r * LOAD_F4;
        int gr = gro + r;
        int gc = gco + c4 * 4;
        float4 v = make_float4(0.f, 0.f, 0.f, 0.f);
        if (gr < IH && gc < IW)
            v = *reinterpret_cast<const float4*>(X + (size_t)gr * IW + gc);
        unsigned xv = (((unsigned)r) >> 1) & 7u;
        *reinterpret_cast<float4*>(sA + r * PITCH_F + (((unsigned)c4 ^ xv) << 2)) = v;
    }
    __syncthreads();

    const int warp = tid >> 5;         // 0..5 -> 16-col strip
    const int lane = tid & 31;
    const int c0 = warp * 4;           // window base in 16B chunks
    const int r0 = lane * 2;           // two output rows per lane

    ull acc0[8], acc1[8];
#pragma unroll
    for (int p = 0; p < 8; ++p) { acc0[p] = 0ULL; acc1[p] = 0ULL; }

    ulonglong2 t[7];
    ull tlast;
    ull a[15], b[14];

    // acc0 (out row r0)   : row r0+j contributes with w[j]
    // acc1 (out row r0+1) : row r0+j contributes with w[j-1]
    //
    // Body order per iteration (in-order issue => prefetch covers the FMAs):
    //   1) expand current raw buffer into a/b   (frees t)
    //   2) load_raw next row into t             (in flight during FMA block)
    //   3) conv_row block on a/b                (~240 FFMA2 of cover)

    // Prologue: fetch row 0.
    load_raw(sA, r0, c0, t, &tlast);

    // j = 0 : only acc0 (w0); prefetch row 1.
    expand(t, tlast, a, b);
    load_raw(sA, r0 + 1, c0, t, &tlast);
    conv_row(acc0, a, b, reinterpret_cast<const ulonglong2*>(sW));

    // j = 1..14 : both accs; prefetch row j+1.
#pragma unroll 1
    for (int j = 1; j <= 14; ++j) {
        expand(t, tlast, a, b);
        load_raw(sA, r0 + j + 1, c0, t, &tlast);
        conv_row(acc0, a, b, reinterpret_cast<const ulonglong2*>(sW + j * 16));
        conv_row(acc1, a, b, reinterpret_cast<const ulonglong2*>(sW + (j - 1) * 16));
    }

    // j = 15 : only acc1 (w14); row 15 already fetched by the j=14 iteration.
    expand(t, tlast, a, b);
    conv_row(acc1, a, b, reinterpret_cast<const ulonglong2*>(sW + 14 * 16));

    // Store: add bias, aligned 8B pairs (OW even -> pairs never straddle edge).
    const unsigned bb = __float_as_uint(bias[0]);
    const ull bpair = mkpair(bb, bb);
    const int oc0 = gco + warp * 16;

    {
        int orow = gro + r0;
        if (orow < OH) {
            float* op = out + (size_t)orow * OW;
#pragma unroll
            for (int p = 0; p < 8; ++p) {
                int oc = oc0 + 2 * p;
                if (oc < OW)
                    *reinterpret_cast<ull*>(op + oc) = add2(acc0[p], bpair);
            }
        }
    }
    {
        int orow = gro + r0 + 1;
        if (orow < OH) {
            float* op = out + (size_t)orow * OW;
#pragma unroll
            for (int p = 0; p < 8; ++p) {
                int oc = oc0 + 2 * p;
                if (oc < OW)
                    *reinterpret_cast<ull*>(op + oc) = add2(acc1[p], bpair);
            }
        }
    }
}

extern "C" void kernel_launch(void* const* d_in, const int* in_sizes, int n_in,
                              void* d_out, int out_size) {
    (void)in_sizes; (void)n_in; (void)out_size;
    const float* X = (const float*)d_in[0];
    const float* W = (const float*)d_in[1];
    const float* b = (const float*)d_in[2];
    float* out = (float*)d_out;

    cudaFuncSetAttribute(conv15_kernel,
                         cudaFuncAttributePreferredSharedMemoryCarveout,
                         cudaSharedmemCarveoutMaxShared);

    dim3 grid((OW + TILE_C - 1) / TILE_C, (OH + TILE_R - 1) / TILE_R);
    conv15_kernel<<<grid, NTHR>>>(X, W, b, out);
}

// round 16
// speedup vs baseline: 1.3406x; 1.2255x over previous
#include <cuda_runtime.h>

#define IH 4096
#define IW 4096
#define OH 4082
#define OW 4082

#define TILE_R 64          // output rows per block (2 rows per lane)
#define TILE_C 96          // output cols per block (6 warps x 16)
#define NTHR   192
#define IN_R   78          // TILE_R + 14 input rows staged
#define PITCH_F 128        // smem row pitch in floats
#define PITCH_B 512
#define LOAD_F4 28         // float4 per staged row

// Scalar conv: one weight row (15 taps) onto 16 float accumulators.
// win[p+m] (p=0..15, m=0..14) -> needs win[0..30]; we load 32.
__device__ __forceinline__ void conv_row_s(float* acc, const float* win,
                                           const float* __restrict__ wrow) {
#pragma unroll
    for (int m = 0; m < 15; ++m) {
        float w = wrow[m];               // broadcast LDS.32 (1 phase)
#pragma unroll
        for (int p = 0; p < 16; ++p)
            acc[p] = fmaf(win[p + m], w, acc[p]);
    }
}

// Load 32 window floats (8 x LDS.128) for input row ir, 16B-XOR-swizzled.
__device__ __forceinline__ void load_win_s(const float* sA, int ir, int c0,
                                           float* win) {
    const unsigned xv = (((unsigned)ir) >> 1) & 7u;
    const char* rowp = reinterpret_cast<const char*>(sA) + ir * PITCH_B;
#pragma unroll
    for (int i = 0; i < 8; ++i) {
        float4 v = *reinterpret_cast<const float4*>(
            rowp + ((unsigned)((c0 + i) ^ xv) << 4));
        win[4 * i + 0] = v.x;
        win[4 * i + 1] = v.y;
        win[4 * i + 2] = v.z;
        win[4 * i + 3] = v.w;
    }
}

__global__ void __launch_bounds__(NTHR, 3)
conv15_kernel(const float* __restrict__ X, const float* __restrict__ Wt,
              const float* __restrict__ bias, float* __restrict__ out) {
    __shared__ float sA[IN_R * PITCH_F];
    __shared__ float sWf[15 * 16];       // weight row j at sWf+16*j (padded)

    const int tid = threadIdx.x;
    const int gro = blockIdx.y * TILE_R;
    const int gco = blockIdx.x * TILE_C;

    // Stage weights (scalar).
    for (int i = tid; i < 225; i += NTHR) {
        int row = i / 15;
        int t = i - row * 15;
        sWf[row * 16 + t] = Wt[i];
    }

    // Stage the input tile with 16B-granularity XOR swizzle: chunk ^ ((row>>1)&7).
    for (int idx = tid; idx < IN_R * LOAD_F4; idx += NTHR) {
        int r = idx / LOAD_F4;
        int c4 = idx - r * LOAD_F4;
        int gr = gro + r;
        int gc = gco + c4 * 4;
        float4 v = make_float4(0.f, 0.f, 0.f, 0.f);
        if (gr < IH && gc < IW)
            v = *reinterpret_cast<const float4*>(X + (size_t)gr * IW + gc);
        unsigned xv = (((unsigned)r) >> 1) & 7u;
        *reinterpret_cast<float4*>(sA + r * PITCH_F + (((unsigned)c4 ^ xv) << 2)) = v;
    }
    __syncthreads();

    const int warp = tid >> 5;         // 0..5 -> 16-col strip
    const int lane = tid & 31;
    const int c0 = warp * 4;           // window base in 16B chunks
    const int r0 = lane * 2;           // two output rows per lane

    float acc0[16], acc1[16];
#pragma unroll
    for (int p = 0; p < 16; ++p) { acc0[p] = 0.f; acc1[p] = 0.f; }

    float win[32];

    // acc0 (out row r0)   : input row r0+j contributes with w[j]
    // acc1 (out row r0+1) : input row r0+j contributes with w[j-1]

    // j = 0 : only acc0 (w0).
    load_win_s(sA, r0, c0, win);
    conv_row_s(acc0, win, sWf);

    // j = 1..14 : both rows share the same window load.
#pragma unroll 1
    for (int j = 1; j <= 14; ++j) {
        load_win_s(sA, r0 + j, c0, win);
        conv_row_s(acc0, win, sWf + j * 16);
        conv_row_s(acc1, win, sWf + (j - 1) * 16);
    }

    // j = 15 : only acc1 (w14).
    load_win_s(sA, r0 + 15, c0, win);
    conv_row_s(acc1, win, sWf + 14 * 16);

    // Store: add bias, 8B float2 pairs (OW even -> pairs never straddle edge).
    const float bv = bias[0];
    const int oc0 = gco + warp * 16;

    {
        int orow = gro + r0;
        if (orow < OH) {
            float* op = out + (size_t)orow * OW;
#pragma unroll
            for (int p = 0; p < 8; ++p) {
                int oc = oc0 + 2 * p;
                if (oc < OW) {
                    float2 v = make_float2(acc0[2 * p] + bv, acc0[2 * p + 1] + bv);
                    *reinterpret_cast<float2*>(op + oc) = v;
                }
            }
        }
    }
    {
        int orow = gro + r0 + 1;
        if (orow < OH) {
            float* op = out + (size_t)orow * OW;
#pragma unroll
            for (int p = 0; p < 8; ++p) {
                int oc = oc0 + 2 * p;
                if (oc < OW) {
                    float2 v = make_float2(acc1[2 * p] + bv, acc1[2 * p + 1] + bv);
                    *reinterpret_cast<float2*>(op + oc) = v;
                }
            }
        }
    }
}

extern "C" void kernel_launch(void* const* d_in, const int* in_sizes, int n_in,
                              void* d_out, int out_size) {
    (void)in_sizes; (void)n_in; (void)out_size;
    const float* X = (const float*)d_in[0];
    const float* W = (const float*)d_in[1];
    const float* b = (const float*)d_in[2];
    float* out = (float*)d_out;

    cudaFuncSetAttribute(conv15_kernel,
                         cudaFuncAttributePreferredSharedMemoryCarveout,
                         cudaSharedmemCarveoutMaxShared);

    dim3 grid((OW + TILE_C - 1) / TILE_C, (OH + TILE_R - 1) / TILE_R);
    conv15_kernel<<<grid, NTHR>>>(X, W, b, out);
}